// round 15
// baseline (speedup 1.0000x reference)
#include <cuda_runtime.h>
#include <cuda_bf16.h>
#include <math.h>
#include <stdint.h>

#define NN 50000
#define EE 800000
#define HH 256
#define FF 128
#define RR 32

// ---------------- persistent device scratch ----------------
__device__ float g_PQ[NN * 256];
__device__ float g_G[NN * FF];
__device__ float g_deg[NN];
__device__ float g_b1f[FF];
__device__ float g_bm[HH];
__device__ __nv_bfloat16 g_Wrt_hi[FF * RR];
__device__ __nv_bfloat16 g_Wrt_lo[FF * RR];
__device__ __nv_bfloat16 g_ntm_hi[FF * HH];
__device__ __nv_bfloat16 g_ntm_lo[FF * HH];
__device__ __nv_bfloat16 g_Wpq_hi[256 * FF];
__device__ __nv_bfloat16 g_Wpq_lo[256 * FF];
__device__ __nv_bfloat16 g_Mo_hi[HH * FF];
__device__ __nv_bfloat16 g_Mo_lo[HH * FF];

// ---------------- ptx helpers ----------------
__device__ __forceinline__ uint32_t smem_u32(const void* p) {
    uint32_t a;
    asm("{ .reg .u64 t; cvta.to.shared.u64 t, %1; cvt.u32.u64 %0, t; }" : "=r"(a) : "l"(p));
    return a;
}
__device__ __forceinline__ void ldsm_x4(uint32_t& r0, uint32_t& r1, uint32_t& r2, uint32_t& r3,
                                        uint32_t addr) {
    asm volatile("ldmatrix.sync.aligned.m8n8.x4.shared.b16 {%0,%1,%2,%3}, [%4];"
                 : "=r"(r0), "=r"(r1), "=r"(r2), "=r"(r3) : "r"(addr));
}
__device__ __forceinline__ void mma16816(float* c, const uint32_t* a, const uint32_t* b) {
    asm volatile(
        "mma.sync.aligned.m16n8k16.row.col.f32.bf16.bf16.f32 "
        "{%0,%1,%2,%3}, {%4,%5,%6,%7}, {%8,%9}, {%0,%1,%2,%3};"
        : "+f"(c[0]), "+f"(c[1]), "+f"(c[2]), "+f"(c[3])
        : "r"(a[0]), "r"(a[1]), "r"(a[2]), "r"(a[3]), "r"(b[0]), "r"(b[1]));
}
__device__ __forceinline__ void split8(const float* v, uint32_t* hw, uint32_t* lw) {
#pragma unroll
    for (int c = 0; c < 4; ++c) {
        __nv_bfloat16 h0 = __float2bfloat16_rn(v[c * 2]);
        __nv_bfloat16 h1 = __float2bfloat16_rn(v[c * 2 + 1]);
        __nv_bfloat162 hh = __halves2bfloat162(h0, h1);
        __nv_bfloat162 ll = __halves2bfloat162(
            __float2bfloat16_rn(v[c * 2]     - __bfloat162float(h0)),
            __float2bfloat16_rn(v[c * 2 + 1] - __bfloat162float(h1)));
        hw[c] = *(uint32_t*)&hh;
        lw[c] = *(uint32_t*)&ll;
    }
}

// ---------------- prep ----------------
__global__ void prep_kernel(const float* __restrict__ l1_w, const float* __restrict__ l1_b,
                            const float* __restrict__ rtm_w, const float* __restrict__ rtm_b,
                            const float* __restrict__ ntm_w) {
    int f = blockIdx.x;      // 128
    int t = threadIdx.x;     // 128
#pragma unroll
    for (int kk = 0; kk < 2; ++kk) {
        int k = t + kk * 128;
        float w = ntm_w[f * HH + k];
        __nv_bfloat16 hi = __float2bfloat16_rn(w);
        g_ntm_hi[f * HH + k] = hi;
        g_ntm_lo[f * HH + k] = __float2bfloat16_rn(w - __bfloat162float(hi));
    }
    {
        float wa = l1_w[f * 384 + t];
        __nv_bfloat16 ha = __float2bfloat16_rn(wa);
        g_Wpq_hi[f * FF + t] = ha;
        g_Wpq_lo[f * FF + t] = __float2bfloat16_rn(wa - __bfloat162float(ha));
        float wb = l1_w[f * 384 + 128 + t];
        __nv_bfloat16 hb = __float2bfloat16_rn(wb);
        g_Wpq_hi[(128 + f) * FF + t] = hb;
        g_Wpq_lo[(128 + f) * FF + t] = __float2bfloat16_rn(wb - __bfloat162float(hb));
    }
    if (t < RR) {
        float s = 0.f;
        for (int c = 0; c < FF; ++c)
            s += l1_w[f * 384 + 256 + c] * rtm_w[c * RR + t];
        __nv_bfloat16 hi = __float2bfloat16_rn(s);
        g_Wrt_hi[f * RR + t] = hi;
        g_Wrt_lo[f * RR + t] = __float2bfloat16_rn(s - __bfloat162float(hi));
    } else if (t == RR) {
        float s = l1_b[f];
        for (int c = 0; c < FF; ++c)
            s += l1_w[f * 384 + 256 + c] * rtm_b[c];
        g_b1f[f] = s;
    }
}

__global__ void prep2_kernel(const float* __restrict__ mtn_w, const float* __restrict__ l2_w,
                             const float* __restrict__ l2_b) {
    __shared__ float mrow[FF];
    int h = blockIdx.x;      // 256
    int k = threadIdx.x;     // 128
    mrow[k] = mtn_w[h * FF + k];
    __syncthreads();
    float s = 0.f;
    for (int f = 0; f < FF; ++f)
        s = fmaf(mrow[f], l2_w[f * FF + k], s);
    __nv_bfloat16 hi = __float2bfloat16_rn(s);
    g_Mo_hi[h * FF + k] = hi;
    g_Mo_lo[h * FF + k] = __float2bfloat16_rn(s - __bfloat162float(hi));
    if (k == 0) {
        float b = 0.f;
        for (int f = 0; f < FF; ++f)
            b = fmaf(mrow[f], l2_b[f], b);
        g_bm[h] = b;
    }
}

__global__ void zero_kernel() {
    float4 z = make_float4(0.f, 0.f, 0.f, 0.f);
    float4* p = (float4*)g_G;
    int total = NN * FF / 4;
    for (int i = blockIdx.x * blockDim.x + threadIdx.x; i < total; i += gridDim.x * blockDim.x)
        p[i] = z;
    for (int i = blockIdx.x * blockDim.x + threadIdx.x; i < NN; i += gridDim.x * blockDim.x)
        g_deg[i] = 0.f;
}

// ---------------- fused node kernel (unchanged from R14 winner) -------------------
#define NX_HI  0
#define NX_LO  34816
#define NW_HI  69632
#define NW_LO  104448
#define NA_HI  0
#define NA_LO  34816
#define NB_HI  69632
#define NB_LO  139264
#define N_SMEM 208896

__global__ __launch_bounds__(512, 1)
void node_kernel(const float* __restrict__ x,
                 const float* __restrict__ ntm_b,
                 const float* __restrict__ norm_g, const float* __restrict__ norm_b) {
    extern __shared__ char sma[];
    uint32_t sbase = smem_u32(sma);
    float* R = (float*)sma;

    int tid = threadIdx.x;
    int wid = tid >> 5, lane = tid & 31;
    int n0 = blockIdx.x * 128;

    int wm = wid >> 2, wn = wid & 3;
    int lrow = lane & 15, acolh = (lane >> 4) * 8;
    int brlo = (lane & 7) | ((lane & 16) >> 1), bcolh = ((lane >> 3) & 1) * 8;
    int lr = lane >> 2, lc = (lane & 3) * 2;

    // phase 1: R = x @ ntm^T (2 chunks of K=128)
    {
        float c[2][4][4];
#pragma unroll
        for (int mi = 0; mi < 2; ++mi)
#pragma unroll
            for (int nt = 0; nt < 4; ++nt)
#pragma unroll
                for (int q = 0; q < 4; ++q) c[mi][nt][q] = 0.f;

        const float4* x4 = (const float4*)x;

        for (int kc = 0; kc < HH; kc += 128) {
            __syncthreads();
#pragma unroll
            for (int it = 0; it < 4; ++it) {
                int idx = tid + it * 512;
                int nl = idx >> 4, kq = idx & 15;
                int n = n0 + nl;
                float4 v0 = make_float4(0.f, 0.f, 0.f, 0.f), v1 = v0;
                if (n < NN) {
                    v0 = x4[n * 64 + kc / 4 + kq * 2];
                    v1 = x4[n * 64 + kc / 4 + kq * 2 + 1];
                }
                float vv[8] = {v0.x, v0.y, v0.z, v0.w, v1.x, v1.y, v1.z, v1.w};
                uint32_t hw[4], lw[4];
                split8(vv, hw, lw);
                *(uint4*)(sma + NX_HI + nl * 272 + kq * 16) = make_uint4(hw[0], hw[1], hw[2], hw[3]);
                *(uint4*)(sma + NX_LO + nl * 272 + kq * 16) = make_uint4(lw[0], lw[1], lw[2], lw[3]);
            }
            const uint4* gh = (const uint4*)g_ntm_hi;
            const uint4* gl = (const uint4*)g_ntm_lo;
#pragma unroll
            for (int it = 0; it < 4; ++it) {
                int idx = tid + it * 512;
                int f = idx >> 4, q = idx & 15;
                *(uint4*)(sma + NW_HI + f * 272 + q * 16) = gh[f * 32 + kc / 8 + q];
                *(uint4*)(sma + NW_LO + f * 272 + q * 16) = gl[f * 32 + kc / 8 + q];
            }
            __syncthreads();
#pragma unroll
            for (int kb = 0; kb < 128; kb += 16) {
                uint32_t ah[2][4], al[2][4];
#pragma unroll
                for (int mi = 0; mi < 2; ++mi) {
                    int arow = wm * 32 + mi * 16 + lrow;
                    ldsm_x4(ah[mi][0], ah[mi][1], ah[mi][2], ah[mi][3],
                            sbase + NX_HI + (uint32_t)(arow * 136 + kb + acolh) * 2);
                    ldsm_x4(al[mi][0], al[mi][1], al[mi][2], al[mi][3],
                            sbase + NX_LO + (uint32_t)(arow * 136 + kb + acolh) * 2);
                }
#pragma unroll
                for (int nb = 0; nb < 2; ++nb) {
                    int brow = wn * 32 + nb * 16 + brlo;
                    uint32_t bh[4], bl[4];
                    ldsm_x4(bh[0], bh[1], bh[2], bh[3],
                            sbase + NW_HI + (uint32_t)(brow * 136 + kb + bcolh) * 2);
                    ldsm_x4(bl[0], bl[1], bl[2], bl[3],
                            sbase + NW_LO + (uint32_t)(brow * 136 + kb + bcolh) * 2);
#pragma unroll
                    for (int mi = 0; mi < 2; ++mi) {
                        mma16816(c[mi][nb * 2],     ah[mi], bh);
                        mma16816(c[mi][nb * 2],     ah[mi], bl);
                        mma16816(c[mi][nb * 2],     al[mi], bh);
                        mma16816(c[mi][nb * 2 + 1], ah[mi], bh + 2);
                        mma16816(c[mi][nb * 2 + 1], ah[mi], bl + 2);
                        mma16816(c[mi][nb * 2 + 1], al[mi], bh + 2);
                    }
                }
            }
        }

        __syncthreads();
#pragma unroll
        for (int mi = 0; mi < 2; ++mi) {
            int row0 = wm * 32 + mi * 16;
#pragma unroll
            for (int nt = 0; nt < 4; ++nt) {
                int col = wn * 32 + nt * 8 + lc;
                *(float2*)&R[(row0 + lr) * 132 + col]     = make_float2(c[mi][nt][0], c[mi][nt][1]);
                *(float2*)&R[(row0 + 8 + lr) * 132 + col] = make_float2(c[mi][nt][2], c[mi][nt][3]);
            }
        }
        __syncthreads();
    }

    // phase 2: LN epilogue -> A tiles; load full B
    {
        int tx = tid & 15, ty = tid >> 4;
        float a[4][8];
#pragma unroll
        for (int r = 0; r < 4; ++r) {
            int row = ty * 4 + r;
            float4 a0 = *(float4*)&R[row * 132 + tx * 8];
            float4 a1 = *(float4*)&R[row * 132 + tx * 8 + 4];
            a[r][0] = a0.x; a[r][1] = a0.y; a[r][2] = a0.z; a[r][3] = a0.w;
            a[r][4] = a1.x; a[r][5] = a1.y; a[r][6] = a1.z; a[r][7] = a1.w;
        }
        __syncthreads();

        {
            const uint4* gh = (const uint4*)g_Wpq_hi;
            const uint4* gl = (const uint4*)g_Wpq_lo;
#pragma unroll
            for (int it = 0; it < 8; ++it) {
                int idx = tid + it * 512;
                int f = idx >> 4, q = idx & 15;
                *(uint4*)(sma + NB_HI + f * 272 + q * 16) = gh[f * 16 + q];
                *(uint4*)(sma + NB_LO + f * 272 + q * 16) = gl[f * 16 + q];
            }
        }

        float bb[8], gg[8], be[8];
#pragma unroll
        for (int cc = 0; cc < 8; ++cc) {
            int f = tx * 8 + cc;
            bb[cc] = ntm_b[f]; gg[cc] = norm_g[f]; be[cc] = norm_b[f];
        }
#pragma unroll
        for (int r = 0; r < 4; ++r) {
            int row = ty * 4 + r;
#pragma unroll
            for (int cc = 0; cc < 8; ++cc) a[r][cc] += bb[cc];

            float s = 0.f;
#pragma unroll
            for (int cc = 0; cc < 8; ++cc) s += a[r][cc];
#pragma unroll
            for (int m = 1; m < 16; m <<= 1) s += __shfl_xor_sync(0xffffffffu, s, m);
            float mu = s * (1.f / FF);
            float v = 0.f;
#pragma unroll
            for (int cc = 0; cc < 8; ++cc) { float d = a[r][cc] - mu; v += d * d; }
#pragma unroll
            for (int m = 1; m < 16; m <<= 1) v += __shfl_xor_sync(0xffffffffu, v, m);
            float inv = rsqrtf(v * (1.f / FF) + 1e-5f);

            float o[8];
#pragma unroll
            for (int cc = 0; cc < 8; ++cc) o[cc] = (a[r][cc] - mu) * inv * gg[cc] + be[cc];
            uint32_t hw[4], lw[4];
            split8(o, hw, lw);
            *(uint4*)(sma + NA_HI + row * 272 + tx * 16) = make_uint4(hw[0], hw[1], hw[2], hw[3]);
            *(uint4*)(sma + NA_LO + row * 272 + tx * 16) = make_uint4(lw[0], lw[1], lw[2], lw[3]);
        }
    }
    __syncthreads();

    // phase 3: PQ = xf @ Wpq^T (both halves, no syncs)
    for (int nh = 0; nh < 2; ++nh) {
        float c[2][4][4];
#pragma unroll
        for (int mi = 0; mi < 2; ++mi)
#pragma unroll
            for (int nt = 0; nt < 4; ++nt)
#pragma unroll
                for (int q = 0; q < 4; ++q) c[mi][nt][q] = 0.f;

#pragma unroll
        for (int kb = 0; kb < 128; kb += 16) {
            uint32_t ah[2][4], al[2][4];
#pragma unroll
            for (int mi = 0; mi < 2; ++mi) {
                int arow = wm * 32 + mi * 16 + lrow;
                ldsm_x4(ah[mi][0], ah[mi][1], ah[mi][2], ah[mi][3],
                        sbase + NA_HI + (uint32_t)(arow * 136 + kb + acolh) * 2);
                ldsm_x4(al[mi][0], al[mi][1], al[mi][2], al[mi][3],
                        sbase + NA_LO + (uint32_t)(arow * 136 + kb + acolh) * 2);
            }
#pragma unroll
            for (int nb = 0; nb < 2; ++nb) {
                int brow = nh * 128 + wn * 32 + nb * 16 + brlo;
                uint32_t bh[4], bl[4];
                ldsm_x4(bh[0], bh[1], bh[2], bh[3],
                        sbase + NB_HI + (uint32_t)(brow * 136 + kb + bcolh) * 2);
                ldsm_x4(bl[0], bl[1], bl[2], bl[3],
                        sbase + NB_LO + (uint32_t)(brow * 136 + kb + bcolh) * 2);
#pragma unroll
                for (int mi = 0; mi < 2; ++mi) {
                    mma16816(c[mi][nb * 2],     ah[mi], bh);
                    mma16816(c[mi][nb * 2],     ah[mi], bl);
                    mma16816(c[mi][nb * 2],     al[mi], bh);
                    mma16816(c[mi][nb * 2 + 1], ah[mi], bh + 2);
                    mma16816(c[mi][nb * 2 + 1], ah[mi], bl + 2);
                    mma16816(c[mi][nb * 2 + 1], al[mi], bh + 2);
                }
            }
        }
#pragma unroll
        for (int mi = 0; mi < 2; ++mi) {
            int row0 = n0 + wm * 32 + mi * 16;
#pragma unroll
            for (int nt = 0; nt < 4; ++nt) {
                int col = nh * 128 + wn * 32 + nt * 8 + lc;
                if (row0 + lr < NN)
                    *(float2*)&g_PQ[(row0 + lr) * 256 + col] = make_float2(c[mi][nt][0], c[mi][nt][1]);
                if (row0 + 8 + lr < NN)
                    *(float2*)&g_PQ[(row0 + 8 + lr) * 256 + col] = make_float2(c[mi][nt][2], c[mi][nt][3]);
            }
        }
    }
}

// ---------------- edge kernel: smem-aliased R, 4 CTAs/SM --------------------------
// A/B mma tiles live in 0..30720; R (fp32 64x132 = 33792 B) aliases them AFTER mma.
#define EO_AHI  0
#define EO_ALO  5120
#define EO_BHI  10240
#define EO_BLO  20480
#define EO_R    0
#define EO_II   33792
#define EO_JJ   34048
#define E_SMEM  34816

__global__ __launch_bounds__(256, 4)
void edge_kernel(const float* __restrict__ rbf, const int* __restrict__ edge_index,
                 const float* __restrict__ ln_g, const float* __restrict__ ln_b) {
    extern __shared__ char sma[];
    uint32_t sbase = smem_u32(sma);
    float* R = (float*)(sma + EO_R);
    int* ii_s = (int*)(sma + EO_II);
    int* jj_s = (int*)(sma + EO_JJ);

    int tid = threadIdx.x;
    int wid = tid >> 5, lane = tid & 31;
    int tx = tid & 15, ty = tid >> 4;
    int e0 = blockIdx.x * 64;

    if (tid < 64) ii_s[tid] = edge_index[e0 + tid];
    else if (tid < 128) jj_s[tid - 64] = edge_index[EE + e0 + (tid - 64)];

    {
        int e = tid >> 2, ks = (tid & 3) * 8;
        const float4* rbf4 = (const float4*)rbf;
        float4 v0 = rbf4[(e0 + e) * 8 + (tid & 3) * 2];
        float4 v1 = rbf4[(e0 + e) * 8 + (tid & 3) * 2 + 1];
        float vv[8] = {v0.x, v0.y, v0.z, v0.w, v1.x, v1.y, v1.z, v1.w};
        uint32_t hw[4], lw[4];
        split8(vv, hw, lw);
        *(uint4*)(sma + EO_AHI + e * 80 + ks * 2) = make_uint4(hw[0], hw[1], hw[2], hw[3]);
        *(uint4*)(sma + EO_ALO + e * 80 + ks * 2) = make_uint4(lw[0], lw[1], lw[2], lw[3]);
    }
    {
        const uint4* gh = (const uint4*)g_Wrt_hi;
        const uint4* gl = (const uint4*)g_Wrt_lo;
        for (int idx = tid; idx < 512; idx += 256) {
            int f = idx >> 2, q = idx & 3;
            *(uint4*)(sma + EO_BHI + f * 80 + q * 16) = gh[idx];
            *(uint4*)(sma + EO_BLO + f * 80 + q * 16) = gl[idx];
        }
    }
    __syncthreads();

    if (tid < 64) atomicAdd(&g_deg[jj_s[tid]], 1.0f);

    // mma: R = rbf @ Wrt^T (3 bf16 products), C kept in regs across alias sync
    {
        int mrow0 = (wid >> 1) * 16;
        int nhalf = (wid & 1) * 64;
        float c[8][4];
#pragma unroll
        for (int nt = 0; nt < 8; ++nt)
#pragma unroll
            for (int q = 0; q < 4; ++q) c[nt][q] = 0.f;

        int arow = mrow0 + (lane & 15);
        int acolh = (lane >> 4) * 8;
        int brlo = ((lane & 7) | ((lane & 16) >> 1));
        int bcolh = ((lane >> 3) & 1) * 8;

#pragma unroll
        for (int kb = 0; kb < 32; kb += 16) {
            uint32_t ah[4], al[4];
            ldsm_x4(ah[0], ah[1], ah[2], ah[3],
                    sbase + EO_AHI + (uint32_t)(arow * 40 + kb + acolh) * 2);
            ldsm_x4(al[0], al[1], al[2], al[3],
                    sbase + EO_ALO + (uint32_t)(arow * 40 + kb + acolh) * 2);
#pragma unroll
            for (int nb = 0; nb < 4; ++nb) {
                int brow = nhalf + nb * 16 + brlo;
                uint32_t bh[4], bl[4];
                ldsm_x4(bh[0], bh[1], bh[2], bh[3],
                        sbase + EO_BHI + (uint32_t)(brow * 40 + kb + bcolh) * 2);
                ldsm_x4(bl[0], bl[1], bl[2], bl[3],
                        sbase + EO_BLO + (uint32_t)(brow * 40 + kb + bcolh) * 2);
                mma16816(c[nb * 2],     ah, bh);
                mma16816(c[nb * 2],     ah, bl);
                mma16816(c[nb * 2],     al, bh);
                mma16816(c[nb * 2 + 1], ah, bh + 2);
                mma16816(c[nb * 2 + 1], ah, bl + 2);
                mma16816(c[nb * 2 + 1], al, bh + 2);
            }
        }
        __syncthreads();   // all mma ldsm reads done before R overwrites A/B tiles
        int lr = lane >> 2, lc = (lane & 3) * 2;
#pragma unroll
        for (int nt = 0; nt < 8; ++nt) {
            int col = nhalf + nt * 8 + lc;
            *(float2*)&R[(mrow0 + lr) * 132 + col]     = make_float2(c[nt][0], c[nt][1]);
            *(float2*)&R[(mrow0 + 8 + lr) * 132 + col] = make_float2(c[nt][2], c[nt][3]);
        }
    }

    float b1r[8], lg[8], lb[8];
#pragma unroll
    for (int c = 0; c < 8; ++c) {
        int f = tx * 8 + c;
        b1r[c] = g_b1f[f]; lg[c] = ln_g[f]; lb[c] = ln_b[f];
    }
    __syncthreads();

    const float4* pq4 = (const float4*)g_PQ;
#pragma unroll
    for (int r = 0; r < 4; ++r) {
        int e = ty * 4 + r;
        int i = ii_s[e], j = jj_s[e];
        float4 r0 = *(float4*)&R[e * 132 + tx * 8];
        float4 r1 = *(float4*)&R[e * 132 + tx * 8 + 4];
        float4 p0 = pq4[i * 64 + tx * 2];
        float4 p1 = pq4[i * 64 + tx * 2 + 1];
        float4 q0 = pq4[j * 64 + 32 + tx * 2];
        float4 q1 = pq4[j * 64 + 32 + tx * 2 + 1];
        float acc[8];
        acc[0] = b1r[0] + r0.x + p0.x + q0.x; acc[1] = b1r[1] + r0.y + p0.y + q0.y;
        acc[2] = b1r[2] + r0.z + p0.z + q0.z; acc[3] = b1r[3] + r0.w + p0.w + q0.w;
        acc[4] = b1r[4] + r1.x + p1.x + q1.x; acc[5] = b1r[5] + r1.y + p1.y + q1.y;
        acc[6] = b1r[6] + r1.z + p1.z + q1.z; acc[7] = b1r[7] + r1.w + p1.w + q1.w;

        float s = 0.f;
#pragma unroll
        for (int c = 0; c < 8; ++c) s += acc[c];
#pragma unroll
        for (int m = 1; m < 16; m <<= 1) s += __shfl_xor_sync(0xffffffffu, s, m);
        float mu = s * (1.f / FF);
        float v = 0.f;
#pragma unroll
        for (int c = 0; c < 8; ++c) { float d = acc[c] - mu; v += d * d; }
#pragma unroll
        for (int m = 1; m < 16; m <<= 1) v += __shfl_xor_sync(0xffffffffu, v, m);
        float inv = rsqrtf(v * (1.f / FF) + 1e-5f);

        float o[8];
#pragma unroll
        for (int c = 0; c < 8; ++c) {
            float h = (acc[c] - mu) * inv * lg[c] + lb[c];
            o[c] = 0.5f * h * (1.0f + erff(h * 0.70710678118654752f));
        }
        float* dst = &g_G[j * FF + tx * 8];
        atomicAdd((float4*)dst,       make_float4(o[0], o[1], o[2], o[3]));
        atomicAdd((float4*)(dst + 4), make_float4(o[4], o[5], o[6], o[7]));
    }
}

// ---------------- out mma kernel (unchanged from R14 winner) ----------------------
#define OO_AHI 0
#define OO_ALO 34816
#define OO_BHI 69632
#define OO_BLO 139264
#define O_SMEM 208896

__global__ __launch_bounds__(512, 1)
void out_kernel(float* __restrict__ out) {
    extern __shared__ char sma[];
    uint32_t sbase = smem_u32(sma);
    int tid = threadIdx.x;
    int wid = tid >> 5, lane = tid & 31;
    int n0 = blockIdx.x * 128;

    int wm = wid >> 2, wn = wid & 3;
    int lrow = lane & 15, acolh = (lane >> 4) * 8;
    int brlo = (lane & 7) | ((lane & 16) >> 1), bcolh = ((lane >> 3) & 1) * 8;
    int lr = lane >> 2, lc = (lane & 3) * 2;

    {
        const float4* g4 = (const float4*)g_G;
#pragma unroll
        for (int it = 0; it < 4; ++it) {
            int idx = tid + it * 512;
            int nl = idx >> 4, q = idx & 15;
            int n = n0 + nl;
            float4 v0 = make_float4(0.f, 0.f, 0.f, 0.f), v1 = v0;
            if (n < NN) {
                v0 = g4[n * 32 + q * 2];
                v1 = g4[n * 32 + q * 2 + 1];
            }
            float vv[8] = {v0.x, v0.y, v0.z, v0.w, v1.x, v1.y, v1.z, v1.w};
            uint32_t hw[4], lw[4];
            split8(vv, hw, lw);
            *(uint4*)(sma + OO_AHI + nl * 272 + q * 16) = make_uint4(hw[0], hw[1], hw[2], hw[3]);
            *(uint4*)(sma + OO_ALO + nl * 272 + q * 16) = make_uint4(lw[0], lw[1], lw[2], lw[3]);
        }
        const uint4* gh = (const uint4*)g_Mo_hi;
        const uint4* gl = (const uint4*)g_Mo_lo;
#pragma unroll
        for (int it = 0; it < 8; ++it) {
            int idx = tid + it * 512;
            int f = idx >> 4, q = idx & 15;
            *(uint4*)(sma + OO_BHI + f * 272 + q * 16) = gh[f * 16 + q];
            *(uint4*)(sma + OO_BLO + f * 272 + q * 16) = gl[f * 16 + q];
        }
    }
    __syncthreads();

    for (int nh = 0; nh < 2; ++nh) {
        float c[2][4][4];
#pragma unroll
        for (int mi = 0; mi < 2; ++mi)
#pragma unroll
            for (int nt = 0; nt < 4; ++nt)
#pragma unroll
                for (int q = 0; q < 4; ++q) c[mi][nt][q] = 0.f;

#pragma unroll
        for (int kb = 0; kb < 128; kb += 16) {
            uint32_t ah[2][4], al[2][4];
#pragma unroll
            for (int mi = 0; mi < 2; ++mi) {
                int arow = wm * 32 + mi * 16 + lrow;
                ldsm_x4(ah[mi][0], ah[mi][1], ah[mi][2], ah[mi][3],
                        sbase + OO_AHI + (uint32_t)(arow * 136 + kb + acolh) * 2);
                ldsm_x4(al[mi][0], al[mi][1], al[mi][2], al[mi][3],
                        sbase + OO_ALO + (uint32_t)(arow * 136 + kb + acolh) * 2);
            }
#pragma unroll
            for (int nb = 0; nb < 2; ++nb) {
                int brow = nh * 128 + wn * 32 + nb * 16 + brlo;
                uint32_t bh[4], bl[4];
                ldsm_x4(bh[0], bh[1], bh[2], bh[3],
                        sbase + OO_BHI + (uint32_t)(brow * 136 + kb + bcolh) * 2);
                ldsm_x4(bl[0], bl[1], bl[2], bl[3],
                        sbase + OO_BLO + (uint32_t)(brow * 136 + kb + bcolh) * 2);
#pragma unroll
                for (int mi = 0; mi < 2; ++mi) {
                    mma16816(c[mi][nb * 2],     ah[mi], bh);
                    mma16816(c[mi][nb * 2],     ah[mi], bl);
                    mma16816(c[mi][nb * 2],     al[mi], bh);
                    mma16816(c[mi][nb * 2 + 1], ah[mi], bh + 2);
                    mma16816(c[mi][nb * 2 + 1], ah[mi], bl + 2);
                    mma16816(c[mi][nb * 2 + 1], al[mi], bh + 2);
                }
            }
        }
#pragma unroll
        for (int mi = 0; mi < 2; ++mi) {
            int row0 = n0 + wm * 32 + mi * 16;
            int n1 = row0 + lr, n2 = row0 + 8 + lr;
            float d1 = (n1 < NN) ? g_deg[n1] : 0.f;
            float d2 = (n2 < NN) ? g_deg[n2] : 0.f;
#pragma unroll
            for (int nt = 0; nt < 4; ++nt) {
                int col = nh * 128 + wn * 32 + nt * 8 + lc;
                float2 bv = *(float2*)&g_bm[col];
                if (n1 < NN)
                    *(float2*)&out[n1 * HH + col] = make_float2(c[mi][nt][0] + d1 * bv.x,
                                                                c[mi][nt][1] + d1 * bv.y);
                if (n2 < NN)
                    *(float2*)&out[n2 * HH + col] = make_float2(c[mi][nt][2] + d2 * bv.x,
                                                                c[mi][nt][3] + d2 * bv.y);
            }
        }
    }
}

// ---------------- launch ----------------
extern "C" void kernel_launch(void* const* d_in, const int* in_sizes, int n_in,
                              void* d_out, int out_size) {
    const float* x      = (const float*)d_in[0];
    const float* rbf    = (const float*)d_in[1];
    const int*   eidx   = (const int*)d_in[2];
    const float* ntm_w  = (const float*)d_in[3];
    const float* ntm_b  = (const float*)d_in[4];
    const float* rtm_w  = (const float*)d_in[5];
    const float* rtm_b  = (const float*)d_in[6];
    const float* norm_g = (const float*)d_in[7];
    const float* norm_b = (const float*)d_in[8];
    const float* l1_w   = (const float*)d_in[9];
    const float* l1_b   = (const float*)d_in[10];
    const float* ln_g   = (const float*)d_in[11];
    const float* ln_b   = (const float*)d_in[12];
    const float* l2_w   = (const float*)d_in[13];
    const float* l2_b   = (const float*)d_in[14];
    const float* mtn_w  = (const float*)d_in[15];
    float* out = (float*)d_out;

    cudaFuncSetAttribute(node_kernel, cudaFuncAttributeMaxDynamicSharedMemorySize, N_SMEM);
    cudaFuncSetAttribute(edge_kernel, cudaFuncAttributeMaxDynamicSharedMemorySize, E_SMEM);
    cudaFuncSetAttribute(out_kernel,  cudaFuncAttributeMaxDynamicSharedMemorySize, O_SMEM);

    zero_kernel<<<2048, 256>>>();
    prep_kernel<<<FF, 128>>>(l1_w, l1_b, rtm_w, rtm_b, ntm_w);
    prep2_kernel<<<HH, 128>>>(mtn_w, l2_w, l2_b);
    node_kernel<<<(NN + 127) / 128, 512, N_SMEM>>>(x, ntm_b, norm_g, norm_b);
    edge_kernel<<<EE / 64, 256, E_SMEM>>>(rbf, eidx, ln_g, ln_b);
    out_kernel<<<(NN + 127) / 128, 512, O_SMEM>>>(out);
}